// round 12
// baseline (speedup 1.0000x reference)
#include <cuda_runtime.h>
#include <cstdint>

#define DIM 1024

// Single fused kernel: every block redundantly computes the 1024-wide softmax
// mask (cheap, hidden under x-load latency), then applies it to its
// 1024-float4 slice of x.
//
// Softmax is computed WITHOUT max-subtraction: mask_param ~ N(0,1), so
// exp() is safely in range and exp(p)/sum(exp(p)) is analytically identical.
// This removes a full reduction tree, a barrier, and ~6 registers.
__global__ void __launch_bounds__(256, 8) fused_mask_mul_kernel(
        const float4* __restrict__ x,
        float4* __restrict__ out,
        const float4* __restrict__ mask_param4,
        const float4* __restrict__ mask_fixed4,
        float4* __restrict__ out_mask4) {
    const int t    = threadIdx.x;         // 0..255
    const int lane = t & 31;
    const int warp = t >> 5;              // 0..7

    // ---- Issue the 4 independent x loads first (latency we hide under) ----
    const long long base = (long long)blockIdx.x * 1024 + t;
    float4 a = x[base];
    float4 b = x[base + 256];
    float4 c = x[base + 512];
    float4 d = x[base + 768];

    // ---- Softmax (no max-subtraction) while loads are in flight ----
    const float4 p = mask_param4[t];      // channels 4t..4t+3 (L2-broadcast)

    float4 e;
    e.x = __expf(p.x);
    e.y = __expf(p.y);
    e.z = __expf(p.z);
    e.w = __expf(p.w);
    float sum = (e.x + e.y) + (e.z + e.w);
    #pragma unroll
    for (int s = 16; s > 0; s >>= 1)
        sum += __shfl_xor_sync(0xffffffffu, sum, s);

    __shared__ float sm[8];
    if (lane == 0) sm[warp] = sum;
    __syncthreads();
    sum = 0.0f;
    #pragma unroll
    for (int w = 0; w < 8; w++) sum += sm[w];

    const float scale = (float)DIM / sum;
    const float4 f = mask_fixed4[t];
    float4 m;
    m.x = scale * e.x * f.x;
    m.y = scale * e.y * f.y;
    m.z = scale * e.z * f.z;
    m.w = scale * e.w * f.w;

    // One block emits the mask tuple element (tail of d_out).
    if (blockIdx.x == 0) out_mask4[t] = m;

    // ---- Apply mask and store ----
    a.x *= m.x; a.y *= m.y; a.z *= m.z; a.w *= m.w;
    b.x *= m.x; b.y *= m.y; b.z *= m.z; b.w *= m.w;
    c.x *= m.x; c.y *= m.y; c.z *= m.z; c.w *= m.w;
    d.x *= m.x; d.y *= m.y; d.z *= m.z; d.w *= m.w;

    out[base]       = a;
    out[base + 256] = b;
    out[base + 512] = c;
    out[base + 768] = d;
}

extern "C" void kernel_launch(void* const* d_in, const int* in_sizes, int n_in,
                              void* d_out, int out_size) {
    const float* x          = (const float*)d_in[0];   // [8, 4096, 1024] f32
    const float* mask_param = (const float*)d_in[1];   // [1024] f32
    const float* mask_fixed = (const float*)d_in[2];   // [1024] f32

    float* out = (float*)d_out;
    const long long n  = (long long)in_sizes[0];       // 33,554,432
    const long long n4 = n / 4;                        // 8,388,608

    const int blocks = (int)(n4 / 1024);               // 8192
    fused_mask_mul_kernel<<<blocks, 256>>>(
        (const float4*)x, (float4*)out,
        (const float4*)mask_param, (const float4*)mask_fixed,
        (float4*)(out + n));                           // mask tail
}